// round 1
// baseline (speedup 1.0000x reference)
#include <cuda_runtime.h>
#include <cuda_bf16.h>

// IIR filterbank: x (128, 4, 65536) f32, b/a (4, 5) f32, out (128, 4, 65536) f32.
// Direct-form-II-transposed, per (batch, filter) sequence.
//
// Strategy: poles all at radius 0.9 (a4 = 0.6561 = 0.9^4), so the filter's
// memory decays as 0.9^n. Chunk the time axis: each thread computes CHUNK
// output samples, warming up its state from zero over the previous WARM
// samples (overlap-save). Truncation error ~ 0.9^256 * Q ~ 1e-9 << 1e-3.

#define T_LEN  65536
#define CHUNK  512
#define WARM   256
#define NSEQ   512                   // 128 batches * 4 filters
#define NCHUNK (T_LEN / CHUNK)       // 128
#define TPB    128

__global__ __launch_bounds__(TPB)
void iir_chunked_kernel(const float* __restrict__ x,
                        const float* __restrict__ bc,
                        const float* __restrict__ ac,
                        float* __restrict__ out)
{
    const int gid   = blockIdx.x * TPB + threadIdx.x;   // 0 .. NSEQ*NCHUNK-1
    const int seq   = gid / NCHUNK;
    const int chunk = gid - seq * NCHUNK;
    const int filt  = seq & 3;                          // layout (batch, filter, T)

    // Load + normalize coefficients (a0 == 1 for these filters, but be general).
    const float a0  = ac[filt * 5 + 0];
    const float inv = 1.0f / a0;
    const float b0 = bc[filt * 5 + 0] * inv;
    const float b1 = bc[filt * 5 + 1] * inv;
    const float b2 = bc[filt * 5 + 2] * inv;
    const float b3 = bc[filt * 5 + 3] * inv;
    const float b4 = bc[filt * 5 + 4] * inv;
    const float a1 = ac[filt * 5 + 1] * inv;
    const float a2 = ac[filt * 5 + 2] * inv;
    const float a3 = ac[filt * 5 + 3] * inv;
    const float a4 = ac[filt * 5 + 4] * inv;

    const float* xs = x   + (size_t)seq * T_LEN;
    float*       ys = out + (size_t)seq * T_LEN;

    const int start  = chunk * CHUNK;
    int wstart = start - WARM;
    if (wstart < 0) wstart = 0;

    float z0 = 0.f, z1 = 0.f, z2 = 0.f, z3 = 0.f;

    // ---- warm-up: run the recurrence, discard outputs ----
    for (int t = wstart; t < start; t += 8) {
        const float4 v0 = *reinterpret_cast<const float4*>(xs + t);
        const float4 v1 = *reinterpret_cast<const float4*>(xs + t + 4);
        float xv[8] = {v0.x, v0.y, v0.z, v0.w, v1.x, v1.y, v1.z, v1.w};
        #pragma unroll
        for (int k = 0; k < 8; k++) {
            const float xn = xv[k];
            const float y   = fmaf(b0, xn, z0);
            const float nz0 = fmaf(-a1, y, fmaf(b1, xn, z1));
            const float nz1 = fmaf(-a2, y, fmaf(b2, xn, z2));
            const float nz2 = fmaf(-a3, y, fmaf(b3, xn, z3));
            const float nz3 = fmaf(-a4, y, b4 * xn);
            z0 = nz0; z1 = nz1; z2 = nz2; z3 = nz3;
        }
    }

    // ---- main: compute and store CHUNK outputs ----
    for (int t = start; t < start + CHUNK; t += 8) {
        const float4 v0 = *reinterpret_cast<const float4*>(xs + t);
        const float4 v1 = *reinterpret_cast<const float4*>(xs + t + 4);
        float xv[8] = {v0.x, v0.y, v0.z, v0.w, v1.x, v1.y, v1.z, v1.w};
        float yv[8];
        #pragma unroll
        for (int k = 0; k < 8; k++) {
            const float xn = xv[k];
            const float y   = fmaf(b0, xn, z0);
            const float nz0 = fmaf(-a1, y, fmaf(b1, xn, z1));
            const float nz1 = fmaf(-a2, y, fmaf(b2, xn, z2));
            const float nz2 = fmaf(-a3, y, fmaf(b3, xn, z3));
            const float nz3 = fmaf(-a4, y, b4 * xn);
            z0 = nz0; z1 = nz1; z2 = nz2; z3 = nz3;
            yv[k] = y;
        }
        *reinterpret_cast<float4*>(ys + t)     = make_float4(yv[0], yv[1], yv[2], yv[3]);
        *reinterpret_cast<float4*>(ys + t + 4) = make_float4(yv[4], yv[5], yv[6], yv[7]);
    }
}

extern "C" void kernel_launch(void* const* d_in, const int* in_sizes, int n_in,
                              void* d_out, int out_size)
{
    const float* x  = (const float*)d_in[0];   // (128, 4, 65536)
    const float* bc = (const float*)d_in[1];   // (4, 5)
    const float* ac = (const float*)d_in[2];   // (4, 5)
    float* out = (float*)d_out;

    const int total  = NSEQ * NCHUNK;          // 65536 threads
    const int blocks = total / TPB;            // 512 blocks
    iir_chunked_kernel<<<blocks, TPB>>>(x, bc, ac, out);
}